// round 14
// baseline (speedup 1.0000x reference)
#include <cuda_runtime.h>
#include <cuda_bf16.h>
#include <stdint.h>

#define VOCAB   1825324
#define BS      4096
#define D       128
#define SEQ     20
#define UNZ     20480
#define NWORDS  57042
#define NB      223              // ceil(NWORDS/256)

// ---------------- device scratch ----------------
__device__ unsigned int g_bitmap[NWORDS];     // zero-init; re-zeroed by tail kernel each call
__device__ unsigned int g_sstate[NB];         // lookback state; zero-init; re-zeroed each call
__device__ int   g_wordpref[NWORDS];
__device__ int   g_posidx[BS];
__device__ int   g_maskdest[BS * SEQ];
__device__ float g_bias[UNZ];
__device__ uint8_t g_Xq[BS * D];              // x * 256 as e4m3
__device__ uint8_t g_Eq[UNZ * D];             // sorted emb * 256 as e4m3

__device__ __forceinline__ int clampv(int v) {
    return v < 0 ? 0 : (v >= VOCAB ? VOCAB - 1 : v);
}
__device__ __forceinline__ uint32_t smem_u32(const void* p) {
    uint32_t a;
    asm("{ .reg .u64 t; cvta.to.shared.u64 t, %1; cvt.u32.u64 %0, t; }" : "=r"(a) : "l"(p));
    return a;
}
__device__ __forceinline__ void stcs(float* p, float v) {
    asm volatile("st.global.cs.f32 [%0], %1;" :: "l"(p), "f"(v));
}
__device__ __forceinline__ void stcs2(float* p, float a, float b) {
    asm volatile("st.global.cs.v2.f32 [%0], {%1,%2};" :: "l"(p), "f"(a), "f"(b));
}
__device__ __forceinline__ void stcs4(float* p, float4 v) {
    asm volatile("st.global.cs.v4.f32 [%0], {%1,%2,%3,%4};"
                 :: "l"(p), "f"(v.x), "f"(v.y), "f"(v.z), "f"(v.w));
}
__device__ __forceinline__ void cp_async16(uint32_t saddr, const void* gaddr) {
    asm volatile("cp.async.cg.shared.global [%0], [%1], 16;" :: "r"(saddr), "l"(gaddr));
}
__device__ __forceinline__ void cp_async_wait_all() {
    asm volatile("cp.async.commit_group;\ncp.async.wait_group 0;" ::: "memory");
}
__device__ __forceinline__ unsigned vld(const unsigned* p) {
    unsigned v;
    asm volatile("ld.volatile.global.u32 %0, [%1];" : "=r"(v) : "l"(p));
    return v;
}
__device__ __forceinline__ void vst(unsigned* p, unsigned v) {
    asm volatile("st.volatile.global.u32 [%0], %1;" :: "l"(p), "r"(v));
}

// pack 4 floats -> 4 e4m3 bytes (byte i = elem i)
__device__ __forceinline__ uint32_t pack_e4m3x4(float f0, float f1, float f2, float f3) {
    uint16_t lo, hi;
    asm("cvt.rn.satfinite.e4m3x2.f32 %0, %1, %2;" : "=h"(lo) : "f"(f1), "f"(f0));
    asm("cvt.rn.satfinite.e4m3x2.f32 %0, %1, %2;" : "=h"(hi) : "f"(f3), "f"(f2));
    return (uint32_t)lo | ((uint32_t)hi << 16);
}

// ---------------- launch 0: set bitmap bits ----------------
__global__ void k_setbits(const int* __restrict__ labels,
                          const int* __restrict__ uneg) {
    int i = blockIdx.x * blockDim.x + threadIdx.x;
    if (i >= UNZ) return;
    int v = clampv(i < BS ? labels[i] : uneg[i - BS]);
    atomicOr(&g_bitmap[v >> 5], 1u << (v & 31));
}

// ---------------- launch 1: fused popcount prefix-scan (decoupled lookback) ----------------
__global__ void k_scan() {
    __shared__ int sred[8];
    __shared__ int s_excl;
    int t = threadIdx.x, lane = t & 31, wid = t >> 5, b = blockIdx.x;
    int w = b * 256 + t;
    int c = (w < NWORDS) ? __popc(g_bitmap[w]) : 0;
    int incl = c;
    for (int o = 1; o < 32; o <<= 1) {
        int x = __shfl_up_sync(0xffffffffu, incl, o);
        if (lane >= o) incl += x;
    }
    if (lane == 31) sred[wid] = incl;
    __syncthreads();
    if (wid == 0) {
        int v = (lane < 8) ? sred[lane] : 0;
        int iv = v;
        for (int o = 1; o < 8; o <<= 1) {
            int x = __shfl_up_sync(0xffffffffu, iv, o);
            if (lane >= o) iv += x;
        }
        int total = __shfl_sync(0xffffffffu, iv, 7);
        if (lane < 8) sred[lane] = iv - v;
        if (lane == 0 && b > 0) vst(&g_sstate[b], (1u << 30) | (unsigned)total);
        int excl = 0;
        if (b > 0) {
            int j = b - 1;
            while (true) {
                int idx = j - lane;
                unsigned s = (idx >= 0) ? vld(&g_sstate[idx]) : (2u << 30);
                while (!__all_sync(0xffffffffu, (s >> 30) != 0u)) {
                    if (idx >= 0) s = vld(&g_sstate[idx]);
                }
                unsigned pm = __ballot_sync(0xffffffffu, (s >> 30) == 2u);
                int val = (int)(s & 0x3FFFFFFFu);
                int contrib;
                if (pm) {
                    int src = __ffs(pm) - 1;
                    contrib = (lane <= src) ? val : 0;
                } else {
                    contrib = val;
                }
                for (int o = 16; o; o >>= 1)
                    contrib += __shfl_down_sync(0xffffffffu, contrib, o);
                excl += __shfl_sync(0xffffffffu, contrib, 0);
                if (pm) break;
                j -= 32;
            }
        }
        if (lane == 0) {
            vst(&g_sstate[b], (2u << 30) | (unsigned)(excl + total));
            s_excl = excl;
        }
    }
    __syncthreads();
    if (w < NWORDS) g_wordpref[w] = s_excl + sred[wid] + (incl - c);
}

__device__ __forceinline__ int rank_of(int v) {
    unsigned int w = g_bitmap[v >> 5];
    int r = g_wordpref[v >> 5] + __popc(w & ((1u << (v & 31)) - 1u));
    return (r < 0) ? 0 : (r >= UNZ ? UNZ - 1 : r);
}

// ---------------- launch 2: prep_all ----------------
// blocks [0,512): x conv (1 uint32 per thread, 131072 total);
// [512,1792): gather by input index (16 rows/block);
// [1792,2112): mask dest
__global__ void k_prep(const float* __restrict__ x, const float* __restrict__ emb,
                       const int* __restrict__ labels, const int* __restrict__ uneg,
                       const int* __restrict__ item_seq,
                       const float* __restrict__ probs,
                       const float* __restrict__ temp, const float* __restrict__ icf) {
    if (blockIdx.x < 512) {
        int i4 = blockIdx.x * 256 + threadIdx.x;      // BS*D/4 = 131072 quads
        float4 v = ((const float4*)x)[i4];
        ((uint32_t*)g_Xq)[i4] = pack_e4m3x4(v.x * 256.f, v.y * 256.f,
                                            v.z * 256.f, v.w * 256.f);
    } else if (blockIdx.x < 1792) {
        int base = (blockIdx.x - 512) * 16 + (threadIdx.x >> 5) * 2;
        int lane = threadIdx.x & 31;
        int i0 = base, i1 = base + 1;
        int v0 = clampv(i0 < BS ? labels[i0] : uneg[i0 - BS]);
        int v1 = clampv(i1 < BS ? labels[i1] : uneg[i1 - BS]);
        int r0 = rank_of(v0);
        int r1 = rank_of(v1);
        float4 f0 = ((const float4*)(emb + (size_t)v0 * D))[lane];
        float4 f1 = ((const float4*)(emb + (size_t)v1 * D))[lane];
        ((uint32_t*)g_Eq)[(size_t)r0 * 32 + lane] =
            pack_e4m3x4(f0.x * 256.f, f0.y * 256.f, f0.z * 256.f, f0.w * 256.f);
        ((uint32_t*)g_Eq)[(size_t)r1 * 32 + lane] =
            pack_e4m3x4(f1.x * 256.f, f1.y * 256.f, f1.z * 256.f, f1.w * 256.f);
        if (lane == 0) {
            float sc = -icf[0] / temp[0];
            g_bias[r0] = sc * logf(probs[v0] + 1e-11f);
            g_bias[r1] = sc * logf(probs[v1] + 1e-11f);
            if (i0 < BS) g_posidx[i0] = r0;
            if (i1 < BS) g_posidx[i1] = r1;
        }
    } else {
        int i = (blockIdx.x - 1792) * 256 + threadIdx.x;
        int b = i / SEQ;
        int tkn = item_seq[i];
        int dest = -1;
        if (tkn >= 0 && tkn < VOCAB) {
            unsigned int w = g_bitmap[tkn >> 5];
            if (w & (1u << (tkn & 31))) {
                int c = rank_of(tkn);
                int pos = rank_of(clampv(labels[b]));
                if (c != pos) dest = (c < pos) ? c + 1 : c;
            }
        }
        g_maskdest[i] = dest;
    }
}

// ---------------- launch 3: FP8 HMMA GEMM, 128x128 tile (R10 structure) ----------------
#define ROWB     144                     // 128B data + 16B pad
#define A_OFF    0
#define B_OFF    (128 * ROWB)            // 18432
#define EPI_STRIDE 132
#define BIAS_OFF 67584                   // after 128x132x4 epi buffer
#define POS_OFF  (BIAS_OFF + 512)
#define SMEM_TOT (POS_OFF + 512)         // 68608

__device__ __forceinline__ void ldsm_x4(uint32_t addr, uint32_t& r0, uint32_t& r1,
                                        uint32_t& r2, uint32_t& r3) {
    asm volatile("ldmatrix.sync.aligned.m8n8.x4.shared.b16 {%0,%1,%2,%3}, [%4];"
                 : "=r"(r0), "=r"(r1), "=r"(r2), "=r"(r3) : "r"(addr));
}
__device__ __forceinline__ void mma_fp8(float* c, uint32_t a0, uint32_t a1,
                                        uint32_t a2, uint32_t a3,
                                        uint32_t b0, uint32_t b1) {
    asm volatile("mma.sync.aligned.m16n8k32.row.col.f32.e4m3.e4m3.f32 "
                 "{%0,%1,%2,%3}, {%4,%5,%6,%7}, {%8,%9}, {%0,%1,%2,%3};"
                 : "+f"(c[0]), "+f"(c[1]), "+f"(c[2]), "+f"(c[3])
                 : "r"(a0), "r"(a1), "r"(a2), "r"(a3), "r"(b0), "r"(b1));
}

__global__ __launch_bounds__(256) void k_gemm_mma(float* __restrict__ out,
                                                  const float* __restrict__ temp) {
    extern __shared__ char sm[];
    uint32_t smb = smem_u32(sm);
    int tid = threadIdx.x;
    int w = tid >> 5, lane = tid & 31;
    int wm = w >> 2, wn = w & 3;           // warp tile 64(M) x 32(N)
    int N0 = blockIdx.x * 128;
    int M0 = blockIdx.y * 128;

    // ---- stage A, B tiles (8 uint4 chunks per 128B row) ----
    const uint4* Asrc = (const uint4*)g_Xq;
    const uint4* Bsrc = (const uint4*)g_Eq;
#pragma unroll
    for (int it = 0; it < 4; it++) {
        int id = tid + it * 256;            // 1024 chunks per tile
        int row = id >> 3, q = id & 7;
        cp_async16(smb + A_OFF + row * ROWB + q * 16, Asrc + (size_t)(M0 + row) * 8 + q);
        cp_async16(smb + B_OFF + row * ROWB + q * 16, Bsrc + (size_t)(N0 + row) * 8 + q);
    }
    if (tid < 128) ((float*)(sm + BIAS_OFF))[tid] = g_bias[N0 + tid];
    else ((int*)(sm + POS_OFF))[tid - 128] = g_posidx[M0 + tid - 128];
    cp_async_wait_all();
    __syncthreads();

    float acc[4][4][4];
#pragma unroll
    for (int i = 0; i < 4; i++)
#pragma unroll
        for (int j = 0; j < 4; j++)
#pragma unroll
            for (int e = 0; e < 4; e++) acc[i][j][e] = 0.f;

    int sel = lane >> 3, r8 = lane & 7;
    // A: m0 rows0-7 kb0-15, m1 rows8-15 kb0-15, m2 rows0-7 kb16-31, m3 rows8-15 kb16-31
    uint32_t a_base = smb + A_OFF + (uint32_t)(wm * 64 + (sel & 1) * 8 + r8) * ROWB
                    + (uint32_t)((sel >> 1) * 16);
    // B: m0 n0-7 kb0-15, m1 n0-7 kb16-31, m2 n8-15 kb0-15, m3 n8-15 kb16-31
    uint32_t b_base = smb + B_OFF + (uint32_t)(wn * 32 + (sel >> 1) * 8 + r8) * ROWB
                    + (uint32_t)((sel & 1) * 16);

#pragma unroll
    for (int kk = 0; kk < 4; kk++) {        // 32 e4m3 per step
        uint32_t a[4][4];
#pragma unroll
        for (int mi = 0; mi < 4; mi++)
            ldsm_x4(a_base + (uint32_t)(mi * 16) * ROWB + kk * 32,
                    a[mi][0], a[mi][1], a[mi][2], a[mi][3]);
        uint32_t b[4][2];
#pragma unroll
        for (int p = 0; p < 2; p++) {
            uint32_t r0, r1, r2, r3;
            ldsm_x4(b_base + (uint32_t)(p * 16) * ROWB + kk * 32, r0, r1, r2, r3);
            b[p * 2][0] = r0; b[p * 2][1] = r1;       // n-tile p*2: k-lo, k-hi
            b[p * 2 + 1][0] = r2; b[p * 2 + 1][1] = r3;
        }
#pragma unroll
        for (int mi = 0; mi < 4; mi++)
#pragma unroll
            for (int nt = 0; nt < 4; nt++)
                mma_fp8(acc[mi][nt], a[mi][0], a[mi][1], a[mi][2], a[mi][3],
                        b[nt][0], b[nt][1]);
    }
    __syncthreads();   // tiles dead; reuse region as epilogue buffer

    // ---- fragments -> smem (fp32, stride 132) ----
    float* epi = (float*)sm;
    int fr = lane >> 2, fc = (lane & 3) * 2;
#pragma unroll
    for (int mi = 0; mi < 4; mi++) {
#pragma unroll
        for (int nt = 0; nt < 4; nt++) {
            int r0 = wm * 64 + mi * 16 + fr;
            int c0 = wn * 32 + nt * 8 + fc;
            *(float2*)&epi[r0 * EPI_STRIDE + c0] = make_float2(acc[mi][nt][0], acc[mi][nt][1]);
            *(float2*)&epi[(r0 + 8) * EPI_STRIDE + c0] = make_float2(acc[mi][nt][2], acc[mi][nt][3]);
        }
    }
    __syncthreads();

    // ---- vectorized epilogue: scale (2^-16, /temp) + bias + positive-col permutation ----
    const float* sbias = (const float*)(sm + BIAS_OFF);
    const int*   spos  = (const int*)(sm + POS_OFF);
    float sc = (1.0f / 65536.0f) / temp[0];
    int tc = (tid & 31) * 4;
    int trp = tid >> 5;
    int cg = N0 + tc;
    float4 b4 = *(const float4*)&sbias[tc];
#pragma unroll 2
    for (int it = 0; it < 16; it++) {
        int row = trp + it * 8;
        float4 v = *(const float4*)&epi[row * EPI_STRIDE + tc];
        v.x = fmaf(v.x, sc, b4.x);
        v.y = fmaf(v.y, sc, b4.y);
        v.z = fmaf(v.z, sc, b4.z);
        v.w = fmaf(v.w, sc, b4.w);
        int pr = spos[row];
        float* dst = out + (size_t)(M0 + row) * UNZ;
        if (pr < cg) {
            stcs4(dst + cg, v);
        } else if (pr > cg + 3) {
            stcs(dst + cg + 1, v.x);
            stcs2(dst + cg + 2, v.y, v.z);
            stcs(dst + cg + 4, v.w);
        } else {
            float vv[4] = {v.x, v.y, v.z, v.w};
#pragma unroll
            for (int e = 0; e < 4; e++) {
                int col = cg + e;
                int dest = (col == pr) ? 0 : (col < pr ? col + 1 : col);
                stcs(dst + dest, vv[e]);
            }
        }
    }
}

// ---------------- launch 4: mask scatter + tail zero + state cleanup ----------------
__global__ void k_mask_tail(float* __restrict__ out,
                            size_t tail_start, int tail_n, int tail_blocks) {
    int bx = blockIdx.x;
    if (bx < 320) {
        int i = bx * 256 + threadIdx.x;
        int d = g_maskdest[i];
        if (d >= 0) out[(size_t)(i / SEQ) * UNZ + d] = 0.0f;
    } else if (bx < 320 + tail_blocks) {
        int i = (bx - 320) * 256 + threadIdx.x;
        if (i < tail_n) out[tail_start + i] = 0.0f;
    } else {
        int i = (bx - 320 - tail_blocks) * 256 + threadIdx.x;
        if (i < NWORDS) g_bitmap[i] = 0u;
        if (i < NB) g_sstate[i] = 0u;
    }
}

// ---------------- launch ----------------
extern "C" void kernel_launch(void* const* d_in, const int* in_sizes, int n_in,
                              void* d_out, int out_size) {
    const float* x      = (const float*)d_in[0];
    const int*   labels = (const int*)d_in[1];
    const int*   iseq   = (const int*)d_in[2];
    const float* probs  = (const float*)d_in[3];
    const int*   uneg   = (const int*)d_in[4];
    const float* emb    = (const float*)d_in[5];
    const float* temp   = (const float*)d_in[6];
    const float* icf    = (const float*)d_in[7];
    float* out = (float*)d_out;

    cudaFuncSetAttribute(k_gemm_mma, cudaFuncAttributeMaxDynamicSharedMemorySize, SMEM_TOT);

    k_setbits<<<(UNZ + 255) / 256, 256>>>(labels, uneg);          // 0
    k_scan<<<NB, 256>>>();                                        // 1
    k_prep<<<2112, 256>>>(x, emb, labels, uneg, iseq,             // 2
                          probs, temp, icf);

    dim3 gg(UNZ / 128, BS / 128);
    k_gemm_mma<<<gg, 256, SMEM_TOT>>>(out, temp);                 // 3  <- profiled slot

    size_t main_n = (size_t)BS * UNZ;
    int tail_n = (int)((size_t)out_size > main_n ? (size_t)out_size - main_n : 0);
    int tail_blocks = (tail_n + 255) / 256;
    k_mask_tail<<<320 + tail_blocks + NB, 256>>>(out, main_n, tail_n, tail_blocks); // 4
}

// round 15
// speedup vs baseline: 1.3691x; 1.3691x over previous
#include <cuda_runtime.h>
#include <cuda_bf16.h>
#include <stdint.h>

#define VOCAB   1825324
#define BS      4096
#define D       128
#define SEQ     20
#define UNZ     20480
#define NWORDS  57042
#define NB      223              // ceil(NWORDS/256)

// ---------------- device scratch ----------------
__device__ unsigned int g_bitmap[NWORDS];     // zero-init; re-zeroed by tail kernel each call
__device__ unsigned int g_sstate[NB];         // lookback state; zero-init; re-zeroed each call
__device__ int   g_wordpref[NWORDS];
__device__ int   g_posidx[BS];
__device__ int   g_maskdest[BS * SEQ];
__device__ float g_bias[UNZ];
__device__ uint8_t g_Xq[BS * D];              // x * 256 as e4m3
__device__ uint8_t g_Eq[UNZ * D];             // sorted emb * 256 as e4m3

__device__ __forceinline__ int clampv(int v) {
    return v < 0 ? 0 : (v >= VOCAB ? VOCAB - 1 : v);
}
__device__ __forceinline__ uint32_t smem_u32(const void* p) {
    uint32_t a;
    asm("{ .reg .u64 t; cvta.to.shared.u64 t, %1; cvt.u32.u64 %0, t; }" : "=r"(a) : "l"(p));
    return a;
}
__device__ __forceinline__ void stcs(float* p, float v) {
    asm volatile("st.global.cs.f32 [%0], %1;" :: "l"(p), "f"(v));
}
__device__ __forceinline__ void stcs2(float* p, float a, float b) {
    asm volatile("st.global.cs.v2.f32 [%0], {%1,%2};" :: "l"(p), "f"(a), "f"(b));
}
__device__ __forceinline__ void stcs4(float* p, float4 v) {
    asm volatile("st.global.cs.v4.f32 [%0], {%1,%2,%3,%4};"
                 :: "l"(p), "f"(v.x), "f"(v.y), "f"(v.z), "f"(v.w));
}
__device__ __forceinline__ void cp_async16(uint32_t saddr, const void* gaddr) {
    asm volatile("cp.async.cg.shared.global [%0], [%1], 16;" :: "r"(saddr), "l"(gaddr));
}
__device__ __forceinline__ void cp_async_wait_all() {
    asm volatile("cp.async.commit_group;\ncp.async.wait_group 0;" ::: "memory");
}
__device__ __forceinline__ unsigned vld(const unsigned* p) {
    unsigned v;
    asm volatile("ld.volatile.global.u32 %0, [%1];" : "=r"(v) : "l"(p));
    return v;
}
__device__ __forceinline__ void vst(unsigned* p, unsigned v) {
    asm volatile("st.volatile.global.u32 [%0], %1;" :: "l"(p), "r"(v));
}

// pack 4 floats -> 4 e4m3 bytes (byte i = elem i)
__device__ __forceinline__ uint32_t pack_e4m3x4(float f0, float f1, float f2, float f3) {
    uint16_t lo, hi;
    asm("cvt.rn.satfinite.e4m3x2.f32 %0, %1, %2;" : "=h"(lo) : "f"(f1), "f"(f0));
    asm("cvt.rn.satfinite.e4m3x2.f32 %0, %1, %2;" : "=h"(hi) : "f"(f3), "f"(f2));
    return (uint32_t)lo | ((uint32_t)hi << 16);
}

// ---------------- launch 0: set bitmap bits ----------------
__global__ void k_setbits(const int* __restrict__ labels,
                          const int* __restrict__ uneg) {
    int i = blockIdx.x * blockDim.x + threadIdx.x;
    if (i >= UNZ) return;
    int v = clampv(i < BS ? labels[i] : uneg[i - BS]);
    atomicOr(&g_bitmap[v >> 5], 1u << (v & 31));
}

// ---------------- launch 1: fused popcount prefix-scan (decoupled lookback) ----------------
__global__ void k_scan() {
    __shared__ int sred[8];
    __shared__ int s_excl;
    int t = threadIdx.x, lane = t & 31, wid = t >> 5, b = blockIdx.x;
    int w = b * 256 + t;
    int c = (w < NWORDS) ? __popc(g_bitmap[w]) : 0;
    int incl = c;
    for (int o = 1; o < 32; o <<= 1) {
        int x = __shfl_up_sync(0xffffffffu, incl, o);
        if (lane >= o) incl += x;
    }
    if (lane == 31) sred[wid] = incl;
    __syncthreads();
    if (wid == 0) {
        int v = (lane < 8) ? sred[lane] : 0;
        int iv = v;
        for (int o = 1; o < 8; o <<= 1) {
            int x = __shfl_up_sync(0xffffffffu, iv, o);
            if (lane >= o) iv += x;
        }
        int total = __shfl_sync(0xffffffffu, iv, 7);
        if (lane < 8) sred[lane] = iv - v;
        if (lane == 0 && b > 0) vst(&g_sstate[b], (1u << 30) | (unsigned)total);
        int excl = 0;
        if (b > 0) {
            int j = b - 1;
            while (true) {
                int idx = j - lane;
                unsigned s = (idx >= 0) ? vld(&g_sstate[idx]) : (2u << 30);
                while (!__all_sync(0xffffffffu, (s >> 30) != 0u)) {
                    if (idx >= 0) s = vld(&g_sstate[idx]);
                }
                unsigned pm = __ballot_sync(0xffffffffu, (s >> 30) == 2u);
                int val = (int)(s & 0x3FFFFFFFu);
                int contrib;
                if (pm) {
                    int src = __ffs(pm) - 1;
                    contrib = (lane <= src) ? val : 0;
                } else {
                    contrib = val;
                }
                for (int o = 16; o; o >>= 1)
                    contrib += __shfl_down_sync(0xffffffffu, contrib, o);
                excl += __shfl_sync(0xffffffffu, contrib, 0);
                if (pm) break;
                j -= 32;
            }
        }
        if (lane == 0) {
            vst(&g_sstate[b], (2u << 30) | (unsigned)(excl + total));
            s_excl = excl;
        }
    }
    __syncthreads();
    if (w < NWORDS) g_wordpref[w] = s_excl + sred[wid] + (incl - c);
}

__device__ __forceinline__ int rank_of(int v) {
    unsigned int w = g_bitmap[v >> 5];
    int r = g_wordpref[v >> 5] + __popc(w & ((1u << (v & 31)) - 1u));
    return (r < 0) ? 0 : (r >= UNZ ? UNZ - 1 : r);
}

// ---------------- launch 2: prep_all ----------------
// blocks [0,512): x conv; [512,1792): gather by input index; [1792,2112): mask dest
__global__ void k_prep(const float* __restrict__ x, const float* __restrict__ emb,
                       const int* __restrict__ labels, const int* __restrict__ uneg,
                       const int* __restrict__ item_seq,
                       const float* __restrict__ probs,
                       const float* __restrict__ temp, const float* __restrict__ icf) {
    if (blockIdx.x < 512) {
        int i4 = blockIdx.x * 256 + threadIdx.x;      // BS*D/4 = 131072 quads
        float4 v = ((const float4*)x)[i4];
        ((uint32_t*)g_Xq)[i4] = pack_e4m3x4(v.x * 256.f, v.y * 256.f,
                                            v.z * 256.f, v.w * 256.f);
    } else if (blockIdx.x < 1792) {
        int base = (blockIdx.x - 512) * 16 + (threadIdx.x >> 5) * 2;
        int lane = threadIdx.x & 31;
        int i0 = base, i1 = base + 1;
        int v0 = clampv(i0 < BS ? labels[i0] : uneg[i0 - BS]);
        int v1 = clampv(i1 < BS ? labels[i1] : uneg[i1 - BS]);
        int r0 = rank_of(v0);
        int r1 = rank_of(v1);
        float4 f0 = ((const float4*)(emb + (size_t)v0 * D))[lane];
        float4 f1 = ((const float4*)(emb + (size_t)v1 * D))[lane];
        ((uint32_t*)g_Eq)[(size_t)r0 * 32 + lane] =
            pack_e4m3x4(f0.x * 256.f, f0.y * 256.f, f0.z * 256.f, f0.w * 256.f);
        ((uint32_t*)g_Eq)[(size_t)r1 * 32 + lane] =
            pack_e4m3x4(f1.x * 256.f, f1.y * 256.f, f1.z * 256.f, f1.w * 256.f);
        if (lane == 0) {
            float sc = -icf[0] / temp[0];
            g_bias[r0] = sc * logf(probs[v0] + 1e-11f);
            g_bias[r1] = sc * logf(probs[v1] + 1e-11f);
            if (i0 < BS) g_posidx[i0] = r0;
            if (i1 < BS) g_posidx[i1] = r1;
        }
    } else {
        int i = (blockIdx.x - 1792) * 256 + threadIdx.x;
        int b = i / SEQ;
        int tkn = item_seq[i];
        int dest = -1;
        if (tkn >= 0 && tkn < VOCAB) {
            unsigned int w = g_bitmap[tkn >> 5];
            if (w & (1u << (tkn & 31))) {
                int c = rank_of(tkn);
                int pos = rank_of(clampv(labels[b]));
                if (c != pos) dest = (c < pos) ? c + 1 : c;
            }
        }
        g_maskdest[i] = dest;
    }
}

// ---------------- launch 3: FP8 HMMA GEMM, 128x128 tile, 2 CTAs/SM forced ----------------
#define ROWB     144                     // 128B data + 16B pad
#define A_OFF    0
#define B_OFF    (128 * ROWB)            // 18432
#define EPI_STRIDE 132
#define BIAS_OFF 67584                   // after 128x132x4 epi buffer
#define POS_OFF  (BIAS_OFF + 512)
#define SMEM_TOT (POS_OFF + 512)         // 68608

__device__ __forceinline__ void ldsm_x4(uint32_t addr, uint32_t& r0, uint32_t& r1,
                                        uint32_t& r2, uint32_t& r3) {
    asm volatile("ldmatrix.sync.aligned.m8n8.x4.shared.b16 {%0,%1,%2,%3}, [%4];"
                 : "=r"(r0), "=r"(r1), "=r"(r2), "=r"(r3) : "r"(addr));
}
__device__ __forceinline__ void mma_fp8(float* c, uint32_t a0, uint32_t a1,
                                        uint32_t a2, uint32_t a3,
                                        uint32_t b0, uint32_t b1) {
    asm volatile("mma.sync.aligned.m16n8k32.row.col.f32.e4m3.e4m3.f32 "
                 "{%0,%1,%2,%3}, {%4,%5,%6,%7}, {%8,%9}, {%0,%1,%2,%3};"
                 : "+f"(c[0]), "+f"(c[1]), "+f"(c[2]), "+f"(c[3])
                 : "r"(a0), "r"(a1), "r"(a2), "r"(a3), "r"(b0), "r"(b1));
}

__global__ __launch_bounds__(256, 2) void k_gemm_mma(float* __restrict__ out,
                                                     const float* __restrict__ temp) {
    extern __shared__ char sm[];
    uint32_t smb = smem_u32(sm);
    int tid = threadIdx.x;
    int w = tid >> 5, lane = tid & 31;
    int wm = w >> 2, wn = w & 3;           // warp tile 64(M) x 32(N)
    int N0 = blockIdx.x * 128;
    int M0 = blockIdx.y * 128;

    // ---- stage A, B tiles (8 uint4 chunks per 128B row) ----
    const uint4* Asrc = (const uint4*)g_Xq;
    const uint4* Bsrc = (const uint4*)g_Eq;
#pragma unroll
    for (int it = 0; it < 4; it++) {
        int id = tid + it * 256;            // 1024 chunks per tile
        int row = id >> 3, q = id & 7;
        cp_async16(smb + A_OFF + row * ROWB + q * 16, Asrc + (size_t)(M0 + row) * 8 + q);
        cp_async16(smb + B_OFF + row * ROWB + q * 16, Bsrc + (size_t)(N0 + row) * 8 + q);
    }
    if (tid < 128) ((float*)(sm + BIAS_OFF))[tid] = g_bias[N0 + tid];
    else ((int*)(sm + POS_OFF))[tid - 128] = g_posidx[M0 + tid - 128];
    cp_async_wait_all();
    __syncthreads();

    float acc[4][4][4];
#pragma unroll
    for (int i = 0; i < 4; i++)
#pragma unroll
        for (int j = 0; j < 4; j++)
#pragma unroll
            for (int e = 0; e < 4; e++) acc[i][j][e] = 0.f;

    int sel = lane >> 3, r8 = lane & 7;
    uint32_t a_base = smb + A_OFF + (uint32_t)(wm * 64 + (sel & 1) * 8 + r8) * ROWB
                    + (uint32_t)((sel >> 1) * 16);
    uint32_t b_base = smb + B_OFF + (uint32_t)(wn * 32 + (sel >> 1) * 8 + r8) * ROWB
                    + (uint32_t)((sel & 1) * 16);

#pragma unroll
    for (int kk = 0; kk < 4; kk++) {        // 32 e4m3 per step
        uint32_t a[4][4];
#pragma unroll
        for (int mi = 0; mi < 4; mi++)
            ldsm_x4(a_base + (uint32_t)(mi * 16) * ROWB + kk * 32,
                    a[mi][0], a[mi][1], a[mi][2], a[mi][3]);
        uint32_t b[4][2];
#pragma unroll
        for (int p = 0; p < 2; p++) {
            uint32_t r0, r1, r2, r3;
            ldsm_x4(b_base + (uint32_t)(p * 16) * ROWB + kk * 32, r0, r1, r2, r3);
            b[p * 2][0] = r0; b[p * 2][1] = r1;
            b[p * 2 + 1][0] = r2; b[p * 2 + 1][1] = r3;
        }
#pragma unroll
        for (int mi = 0; mi < 4; mi++)
#pragma unroll
            for (int nt = 0; nt < 4; nt++)
                mma_fp8(acc[mi][nt], a[mi][0], a[mi][1], a[mi][2], a[mi][3],
                        b[nt][0], b[nt][1]);
    }
    __syncthreads();   // tiles dead; reuse region as epilogue buffer

    // ---- fragments -> smem (fp32, stride 132) ----
    float* epi = (float*)sm;
    int fr = lane >> 2, fc = (lane & 3) * 2;
#pragma unroll
    for (int mi = 0; mi < 4; mi++) {
#pragma unroll
        for (int nt = 0; nt < 4; nt++) {
            int r0 = wm * 64 + mi * 16 + fr;
            int c0 = wn * 32 + nt * 8 + fc;
            *(float2*)&epi[r0 * EPI_STRIDE + c0] = make_float2(acc[mi][nt][0], acc[mi][nt][1]);
            *(float2*)&epi[(r0 + 8) * EPI_STRIDE + c0] = make_float2(acc[mi][nt][2], acc[mi][nt][3]);
        }
    }
    __syncthreads();

    // ---- vectorized epilogue: scale (2^-16, /temp) + bias + positive-col permutation ----
    const float* sbias = (const float*)(sm + BIAS_OFF);
    const int*   spos  = (const int*)(sm + POS_OFF);
    float sc = (1.0f / 65536.0f) / temp[0];
    int tc = (tid & 31) * 4;
    int trp = tid >> 5;
    int cg = N0 + tc;
    float4 b4 = *(const float4*)&sbias[tc];
#pragma unroll 2
    for (int it = 0; it < 16; it++) {
        int row = trp + it * 8;
        float4 v = *(const float4*)&epi[row * EPI_STRIDE + tc];
        v.x = fmaf(v.x, sc, b4.x);
        v.y = fmaf(v.y, sc, b4.y);
        v.z = fmaf(v.z, sc, b4.z);
        v.w = fmaf(v.w, sc, b4.w);
        int pr = spos[row];
        float* dst = out + (size_t)(M0 + row) * UNZ;
        if (pr < cg) {
            stcs4(dst + cg, v);
        } else if (pr > cg + 3) {
            stcs(dst + cg + 1, v.x);
            stcs2(dst + cg + 2, v.y, v.z);
            stcs(dst + cg + 4, v.w);
        } else {
            float vv[4] = {v.x, v.y, v.z, v.w};
#pragma unroll
            for (int e = 0; e < 4; e++) {
                int col = cg + e;
                int dest = (col == pr) ? 0 : (col < pr ? col + 1 : col);
                stcs(dst + dest, vv[e]);
            }
        }
    }
}

// ---------------- launch 4: mask scatter + tail zero + state cleanup ----------------
__global__ void k_mask_tail(float* __restrict__ out,
                            size_t tail_start, int tail_n, int tail_blocks) {
    int bx = blockIdx.x;
    if (bx < 320) {
        int i = bx * 256 + threadIdx.x;
        int d = g_maskdest[i];
        if (d >= 0) out[(size_t)(i / SEQ) * UNZ + d] = 0.0f;
    } else if (bx < 320 + tail_blocks) {
        int i = (bx - 320) * 256 + threadIdx.x;
        if (i < tail_n) out[tail_start + i] = 0.0f;
    } else {
        int i = (bx - 320 - tail_blocks) * 256 + threadIdx.x;
        if (i < NWORDS) g_bitmap[i] = 0u;
        if (i < NB) g_sstate[i] = 0u;
    }
}

// ---------------- launch ----------------
extern "C" void kernel_launch(void* const* d_in, const int* in_sizes, int n_in,
                              void* d_out, int out_size) {
    const float* x      = (const float*)d_in[0];
    const int*   labels = (const int*)d_in[1];
    const int*   iseq   = (const int*)d_in[2];
    const float* probs  = (const float*)d_in[3];
    const int*   uneg   = (const int*)d_in[4];
    const float* emb    = (const float*)d_in[5];
    const float* temp   = (const float*)d_in[6];
    const float* icf    = (const float*)d_in[7];
    float* out = (float*)d_out;

    cudaFuncSetAttribute(k_gemm_mma, cudaFuncAttributeMaxDynamicSharedMemorySize, SMEM_TOT);

    k_setbits<<<(UNZ + 255) / 256, 256>>>(labels, uneg);          // 0
    k_scan<<<NB, 256>>>();                                        // 1
    k_prep<<<2112, 256>>>(x, emb, labels, uneg, iseq,             // 2
                          probs, temp, icf);

    dim3 gg(UNZ / 128, BS / 128);
    k_gemm_mma<<<gg, 256, SMEM_TOT>>>(out, temp);                 // 3  <- profiled slot

    size_t main_n = (size_t)BS * UNZ;
    int tail_n = (int)((size_t)out_size > main_n ? (size_t)out_size - main_n : 0);
    int tail_blocks = (tail_n + 255) / 256;
    k_mask_tail<<<320 + tail_blocks + NB, 256>>>(out, main_n, tail_n, tail_blocks); // 4
}